// round 10
// baseline (speedup 1.0000x reference)
#include <cuda_runtime.h>
#include <cuda_bf16.h>

// feature_maps: [1, 200, 304, 256] fp32 (NHWC) | proposals: [N,4] (x1,y1,x2,y2)
// image_shape: [2] int32 | output: [N, 7, 7, 256] fp32
#define HF   200
#define WF   304
#define CC   256
#define CROP 14
#define POOL 7

// Weight-form axis: weights pre-folded with validity, indices pre-scaled to
// element offsets (y: i*WF*CC, x: i*CC).
struct __align__(16) Axis {
    int   o0;   // clipped floor index * stride
    int   o1;   // clipped (floor+1) index * stride
    float w0;   // (1-l) * valid
    float w1;   //   l   * valid
};

__device__ __forceinline__ float4 ld4(const float* p) { return *(const float4*)p; }

__device__ __forceinline__ float4 max4(float4 a, float4 b) {
    float4 r;
    r.x = fmaxf(a.x, b.x);
    r.y = fmaxf(a.y, b.y);
    r.z = fmaxf(a.z, b.z);
    r.w = fmaxf(a.w, b.w);
    return r;
}

// a*wa + b*wb per component
__device__ __forceinline__ float4 wsum(float4 a, float wa, float4 b, float wb) {
    float4 r;
    r.x = fmaf(b.x, wb, a.x * wa);
    r.y = fmaf(b.y, wb, a.y * wa);
    r.z = fmaf(b.z, wb, a.z * wa);
    r.w = fmaf(b.w, wb, a.w * wa);
    return r;
}

// Load the UX unique columns of one feature row and produce both x-samples'
// horizontal combinations. Column mapping:
//   UX==2: xs0=(v0,v1) xs1=(v0,v1) | UX==3: xs1=(v1,v2) | UX==4: xs1=(v2,v3)
template<int UX>
__device__ __forceinline__ void row_x(const float* row,
                                      int c0, int c1, int c2, int c3,
                                      float a0, float a1, float b0, float b1,
                                      float4& X0, float4& X1)
{
    const float4 v0 = ld4(row + c0);
    const float4 v1 = ld4(row + c1);
    float4 v2 = v1, v3 = v1;
    if (UX >= 3) v2 = ld4(row + c2);
    if (UX >= 4) v3 = ld4(row + c3);
    X0 = wsum(v0, a0, v1, a1);
    if (UX == 2)      X1 = wsum(v0, b0, v1, b1);
    else if (UX == 3) X1 = wsum(v1, b0, v2, b1);
    else              X1 = wsum(v2, b0, v3, b1);
}

// One pooled cell with UY unique rows x UX unique cols (loads = UY*UX <= 16).
// Row mapping: sample0 rows=(0,1); sample1: UY==2 ->(0,1), UY==3 ->(1,2), UY==4 ->(2,3)
template<int UY, int UX>
__device__ __forceinline__ float4 cell_body(const float* fmc,
                                            Axis ay0, Axis ay1, Axis ax0, Axis ax1)
{
    const int c0 = ax0.o0, c1 = ax0.o1;
    const int c2 = (UX == 3) ? ax1.o1 : ax1.o0;
    const int c3 = ax1.o1;
    const float xa0 = ax0.w0, xa1 = ax0.w1;
    const float xb0 = ax1.w0, xb1 = ax1.w1;

    const int r0 = ay0.o0, r1 = ay0.o1;
    const int r2 = (UY == 3) ? ay1.o1 : ay1.o0;
    const int r3 = ay1.o1;

    float4 X0a, X1a, X0b, X1b, X0c, X1c, X0d, X1d;
    row_x<UX>(fmc + r0, c0, c1, c2, c3, xa0, xa1, xb0, xb1, X0a, X1a);
    row_x<UX>(fmc + r1, c0, c1, c2, c3, xa0, xa1, xb0, xb1, X0b, X1b);
    if (UY >= 3) row_x<UX>(fmc + r2, c0, c1, c2, c3, xa0, xa1, xb0, xb1, X0c, X1c);
    if (UY >= 4) row_x<UX>(fmc + r3, c0, c1, c2, c3, xa0, xa1, xb0, xb1, X0d, X1d);

    // sample0 uses rows (r0, r1)
    const float4 s00 = wsum(X0a, ay0.w0, X0b, ay0.w1);
    const float4 s01 = wsum(X1a, ay0.w0, X1b, ay0.w1);
    float4 s10, s11;
    if (UY == 2)      { s10 = wsum(X0a, ay1.w0, X0b, ay1.w1); s11 = wsum(X1a, ay1.w0, X1b, ay1.w1); }
    else if (UY == 3) { s10 = wsum(X0b, ay1.w0, X0c, ay1.w1); s11 = wsum(X1b, ay1.w0, X1c, ay1.w1); }
    else              { s10 = wsum(X0c, ay1.w0, X0d, ay1.w1); s11 = wsum(X1c, ay1.w0, X1d, ay1.w1); }

    return max4(max4(s00, s01), max4(s10, s11));
}

// R7 decomposition: 13 groups of 4 adjacent cells split over grid.y=4
// (cross-warp same-row reuse), 64x4 block, 64-reg budget.
__global__ __launch_bounds__(256, 4)
void roi_pool_kernel(const float* __restrict__ fm,
                     const float* __restrict__ props,
                     const int*   __restrict__ ishape,
                     float* __restrict__ out,
                     int N)
{
    __shared__ Axis sy[CROP];
    __shared__ Axis sx[CROP];

    const int n   = blockIdx.x;
    const int by  = blockIdx.y;                     // 0..3: cell-group quarter
    const int tx  = threadIdx.x;                    // 0..63: channel group (float4)
    const int ty  = threadIdx.y;                    // 0..3 : cell within group
    const int tid = ty * 64 + tx;

    // ---- Per-box axis parameters (28 threads, once per CTA) ----
    if (tid < 2 * CROP) {
        const float h = (float)ishape[0];
        const float w = (float)ishape[1];
        const float* p = props + (size_t)n * 4;
        const bool isY = (tid < CROP);
        const int  i   = isY ? tid : tid - CROP;
        const float c1 = isY ? (p[1] / h) : (p[0] / w);
        const float c2 = isY ? (p[3] / h) : (p[2] / w);
        const float D  = isY ? (float)(HF - 1) : (float)(WF - 1);
        const int   stride = isY ? (WF * CC) : CC;
        const float step = (c2 - c1) * D / (float)(CROP - 1);
        const float s    = fmaf((float)i, step, c1 * D);
        const float f    = floorf(s);
        int i0 = (int)f;
        i0 = max(0, min(i0, (int)D));
        const int i1 = min(i0 + 1, (int)D);
        const float l = s - f;
        const float v = (s >= 0.0f && s <= D) ? 1.0f : 0.0f;
        Axis a;
        a.o0 = i0 * stride;
        a.o1 = i1 * stride;
        a.w0 = (1.0f - l) * v;
        a.w1 = l * v;
        if (isY) sy[i] = a; else sx[i] = a;
    }
    __syncthreads();

    const float* fmc = fm + tx * 4;   // fold channel offset into the base pointer

    const int gstart = (13 * by) >> 2;        // 0,3,6,9
    const int gend   = (13 * (by + 1)) >> 2;  // 3,6,9,13

    for (int g = gstart; g < gend; ++g) {
        const int cell = 4 * g + ty;          // 4 adjacent cells per step
        if (cell >= POOL * POOL) break;

        const int py = cell / POOL;
        const int px = cell - py * POOL;

        const Axis ax0 = sx[2 * px];
        const Axis ax1 = sx[2 * px + 1];
        const Axis ay0 = sy[2 * py];
        const Axis ay1 = sy[2 * py + 1];

        // Unique corner-grid size per axis (warp-uniform: smem values)
        const int UX = (ax1.o0 == ax0.o0) ? 2 : (ax1.o0 == ax0.o1) ? 3 : 4;
        const int UY = (ay1.o0 == ay0.o0) ? 2 : (ay1.o0 == ay0.o1) ? 3 : 4;

        float4 m;
        if (UY == 2) {
            m = (UX == 2) ? cell_body<2, 2>(fmc, ay0, ay1, ax0, ax1)
              : (UX == 3) ? cell_body<2, 3>(fmc, ay0, ay1, ax0, ax1)
                          : cell_body<2, 4>(fmc, ay0, ay1, ax0, ax1);
        } else if (UY == 3) {
            m = (UX == 2) ? cell_body<3, 2>(fmc, ay0, ay1, ax0, ax1)
              : (UX == 3) ? cell_body<3, 3>(fmc, ay0, ay1, ax0, ax1)
                          : cell_body<3, 4>(fmc, ay0, ay1, ax0, ax1);
        } else {
            m = (UX == 2) ? cell_body<4, 2>(fmc, ay0, ay1, ax0, ax1)
              : (UX == 3) ? cell_body<4, 3>(fmc, ay0, ay1, ax0, ax1)
                          : cell_body<4, 4>(fmc, ay0, ay1, ax0, ax1);
        }

        float* o = out + (((size_t)n * (POOL * POOL)) + cell) * CC + tx * 4;
        __stcs((float4*)o, m);   // streaming store: keep the feature map in L2
    }
}

extern "C" void kernel_launch(void* const* d_in, const int* in_sizes, int n_in,
                              void* d_out, int out_size) {
    const float* fm     = (const float*)d_in[0];
    const float* props  = (const float*)d_in[1];
    const int*   ishape = (const int*)  d_in[2];
    float*       out    = (float*)d_out;

    const int N = in_sizes[1] / 4;   // proposals: [N, 4]

    dim3 block(64, 4, 1);
    dim3 grid(N, 4, 1);
    roi_pool_kernel<<<grid, block>>>(fm, props, ishape, out, N);
}

// round 11
// speedup vs baseline: 1.1203x; 1.1203x over previous
#include <cuda_runtime.h>
#include <cuda_bf16.h>

// feature_maps: [1, 200, 304, 256] fp32 (NHWC) | proposals: [N,4] (x1,y1,x2,y2)
// image_shape: [2] int32 | output: [N, 7, 7, 256] fp32
#define HF   200
#define WF   304
#define CC   256
#define CROP 14
#define POOL 7

struct __align__(16) Axis {
    int   o0;   // clipped floor index * stride (elements)
    int   o1;   // clipped (floor+1) index * stride
    float l;    // interpolation fraction
    float v;    // validity (1.0f / 0.0f)
};

__device__ __forceinline__ float4 lerp4(float4 a, float4 b, float t) {
    float4 r;
    r.x = fmaf(b.x - a.x, t, a.x);
    r.y = fmaf(b.y - a.y, t, a.y);
    r.z = fmaf(b.z - a.z, t, a.z);
    r.w = fmaf(b.w - a.w, t, a.w);
    return r;
}

__device__ __forceinline__ float4 max4(float4 a, float4 b) {
    float4 r;
    r.x = fmaxf(a.x, b.x);
    r.y = fmaxf(a.y, b.y);
    r.z = fmaxf(a.z, b.z);
    r.w = fmaxf(a.w, b.w);
    return r;
}

__device__ __forceinline__ float4 scale4(float4 a, float s) {
    float4 r; r.x = a.x * s; r.y = a.y * s; r.z = a.z * s; r.w = a.w * s;
    return r;
}

// R7 winner: 13 groups of 4 adjacent cells, split over 4 CTAs in grid.y.
// 64x4 block, 64-reg budget (4 CTAs/SM), flat 8-load batches, __stcs stores.
__global__ __launch_bounds__(256, 4)
void roi_pool_kernel(const float* __restrict__ fm,
                     const float* __restrict__ props,
                     const int*   __restrict__ ishape,
                     float* __restrict__ out,
                     int N)
{
    __shared__ Axis sy[CROP];
    __shared__ Axis sx[CROP];

    const int n   = blockIdx.x;
    const int by  = blockIdx.y;                     // 0..3: cell-group quarter
    const int tx  = threadIdx.x;                    // 0..63: channel group (float4)
    const int ty  = threadIdx.y;                    // 0..3 : cell within group
    const int tid = ty * 64 + tx;

    // ---- Per-box axis parameters (28 threads, once per CTA) ----
    if (tid < 2 * CROP) {
        const float h = (float)ishape[0];
        const float w = (float)ishape[1];
        const float* p = props + (size_t)n * 4;
        const bool isY = (tid < CROP);
        const int  i   = isY ? tid : tid - CROP;
        const float c1 = isY ? (p[1] / h) : (p[0] / w);
        const float c2 = isY ? (p[3] / h) : (p[2] / w);
        const float D  = isY ? (float)(HF - 1) : (float)(WF - 1);
        const int   stride = isY ? (WF * CC) : CC;
        const float step = (c2 - c1) * D / (float)(CROP - 1);
        const float s    = fmaf((float)i, step, c1 * D);
        const float f    = floorf(s);
        int i0 = (int)f;
        i0 = max(0, min(i0, (int)D));
        const int i1 = min(i0 + 1, (int)D);
        Axis a;
        a.o0 = i0 * stride;
        a.o1 = i1 * stride;
        a.l  = s - f;
        a.v  = (s >= 0.0f && s <= D) ? 1.0f : 0.0f;
        if (isY) sy[i] = a; else sx[i] = a;
    }
    __syncthreads();

    const float* fmc = fm + tx * 4;   // fold channel offset into the base pointer

    const int gstart = (13 * by) >> 2;        // 0,3,6,9
    const int gend   = (13 * (by + 1)) >> 2;  // 3,6,9,13

    for (int g = gstart; g < gend; ++g) {
        const int cell = 4 * g + ty;          // 4 adjacent cells per iteration (cross-warp reuse)
        if (cell >= POOL * POOL) break;

        const int py = cell / POOL;
        const int px = cell - py * POOL;

        const Axis ax0 = sx[2 * px];
        const Axis ax1 = sx[2 * px + 1];

        float4 m = make_float4(-__FLT_MAX__, -__FLT_MAX__, -__FLT_MAX__, -__FLT_MAX__);

        #pragma unroll
        for (int dy = 0; dy < 2; ++dy) {
            const Axis ay = sy[2 * py + dy];
            const float* r0 = fmc + ay.o0;
            const float* r1 = fmc + ay.o1;

            // front-batch all 8 loads for this y-sample before any math
            const float4 a00 = *(const float4*)(r0 + ax0.o0);
            const float4 a01 = *(const float4*)(r0 + ax0.o1);
            const float4 a10 = *(const float4*)(r1 + ax0.o0);
            const float4 a11 = *(const float4*)(r1 + ax0.o1);
            const float4 b00 = *(const float4*)(r0 + ax1.o0);
            const float4 b01 = *(const float4*)(r0 + ax1.o1);
            const float4 b10 = *(const float4*)(r1 + ax1.o0);
            const float4 b11 = *(const float4*)(r1 + ax1.o1);

            const float ly = ay.l;
            const float va = ay.v * ax0.v;
            const float vb = ay.v * ax1.v;

            float4 ta = lerp4(a00, a01, ax0.l);
            float4 ba = lerp4(a10, a11, ax0.l);
            float4 sa = scale4(lerp4(ta, ba, ly), va);
            m = max4(m, sa);

            float4 tb = lerp4(b00, b01, ax1.l);
            float4 bb = lerp4(b10, b11, ax1.l);
            float4 sb = scale4(lerp4(tb, bb, ly), vb);
            m = max4(m, sb);
        }

        float* o = out + (((size_t)n * (POOL * POOL)) + cell) * CC + tx * 4;
        __stcs((float4*)o, m);   // streaming store: keep the feature map in L2
    }
}

extern "C" void kernel_launch(void* const* d_in, const int* in_sizes, int n_in,
                              void* d_out, int out_size) {
    const float* fm     = (const float*)d_in[0];
    const float* props  = (const float*)d_in[1];
    const int*   ishape = (const int*)  d_in[2];
    float*       out    = (float*)d_out;

    const int N = in_sizes[1] / 4;   // proposals: [N, 4]

    // Guarantee the full 228 KB unified L1 is data cache (smem use is 448 B).
    // Host-side attribute set: executes at capture time, zero cost on replay.
    cudaFuncSetAttribute(roi_pool_kernel,
                         cudaFuncAttributePreferredSharedMemoryCarveout,
                         cudaSharedmemCarveoutMaxL1);

    dim3 block(64, 4, 1);
    dim3 grid(N, 4, 1);
    roi_pool_kernel<<<grid, block>>>(fm, props, ishape, out, N);
}